// round 1
// baseline (speedup 1.0000x reference)
#include <cuda_runtime.h>
#include <cuda_bf16.h>
#include <math.h>

#define NN 4096
#define FF 512
#define RR 64
#define HH 8
#define HR 512          // H*R
#define EPSB 0.01f
#define ALPHA 0.2f

// Scratch (device globals: allocation-free per harness rules)
__device__ float g_hidden[NN * HR];   // [n][h*64+r]  (8 MB)
__device__ float g_asrc[HH * NN];
__device__ float g_adst[HH * NN];

// ---------------------------------------------------------------------------
// Kernel 1: g_hidden[n][h*64+r] = sum_f node[n][f] * W[h][f][r]
// C[4096x512] = A[4096x512] * B[512x512], B[f][h*64+r] = W[h*512*64 + f*64 + r]
// Tiles: BM=128, BN=64 (one head per block col), BK=16, 256 threads, 8x4 micro.
// ---------------------------------------------------------------------------
__global__ __launch_bounds__(256) void gemm_hidden_kernel(
    const float* __restrict__ A, const float* __restrict__ W)
{
    __shared__ float As[16][128];
    __shared__ float Bs[16][64];

    const int tid = threadIdx.x;
    const int tx = tid & 15;        // 16 cols of 4
    const int ty = tid >> 4;        // 16 rows of 8
    const int bn = blockIdx.x * 64; // head = blockIdx.x
    const int bm = blockIdx.y * 128;
    const float* Wh = W + (size_t)blockIdx.x * (FF * RR);

    float acc[8][4];
    #pragma unroll
    for (int i = 0; i < 8; i++)
        #pragma unroll
        for (int j = 0; j < 4; j++) acc[i][j] = 0.f;

    for (int k0 = 0; k0 < FF; k0 += 16) {
        // Load A tile 128x16 (transposed into As[k][m])
        #pragma unroll
        for (int q = 0; q < 2; q++) {
            int idx = tid * 2 + q;          // 0..511
            int row = idx >> 2;             // 0..127
            int c4  = (idx & 3) << 2;       // 0,4,8,12
            float4 v = *reinterpret_cast<const float4*>(
                A + (size_t)(bm + row) * FF + k0 + c4);
            As[c4 + 0][row] = v.x;
            As[c4 + 1][row] = v.y;
            As[c4 + 2][row] = v.z;
            As[c4 + 3][row] = v.w;
        }
        // Load B tile 16x64
        {
            int f = tid >> 4;               // 0..15
            int c = (tid & 15) << 2;        // 0..60
            float4 v = *reinterpret_cast<const float4*>(
                Wh + (size_t)(k0 + f) * RR + c);
            *reinterpret_cast<float4*>(&Bs[f][c]) = v;
        }
        __syncthreads();

        #pragma unroll
        for (int k = 0; k < 16; k++) {
            float4 a0 = *reinterpret_cast<const float4*>(&As[k][ty * 8]);
            float4 a1 = *reinterpret_cast<const float4*>(&As[k][ty * 8 + 4]);
            float4 bv = *reinterpret_cast<const float4*>(&Bs[k][tx * 4]);
            float a[8] = {a0.x, a0.y, a0.z, a0.w, a1.x, a1.y, a1.z, a1.w};
            float b[4] = {bv.x, bv.y, bv.z, bv.w};
            #pragma unroll
            for (int i = 0; i < 8; i++)
                #pragma unroll
                for (int j = 0; j < 4; j++)
                    acc[i][j] = fmaf(a[i], b[j], acc[i][j]);
        }
        __syncthreads();
    }

    #pragma unroll
    for (int i = 0; i < 8; i++) {
        int row = bm + ty * 8 + i;
        float4 o = make_float4(acc[i][0], acc[i][1], acc[i][2], acc[i][3]);
        *reinterpret_cast<float4*>(
            &g_hidden[(size_t)row * HR + bn + tx * 4]) = o;
    }
}

// ---------------------------------------------------------------------------
// Kernel 2: a_src[h][n] = hidden[h,n,:] . att[h,:R] ; a_dst with att[h,R:]
// One block per node, warp w handles head w (2 elems/lane, shfl reduce).
// ---------------------------------------------------------------------------
__global__ __launch_bounds__(256) void src_dst_kernel(const float* __restrict__ att)
{
    const int n = blockIdx.x;
    const int wid = threadIdx.x >> 5;
    const int lane = threadIdx.x & 31;
    const float* hrow = g_hidden + (size_t)n * HR + wid * RR;
    float h0 = hrow[lane], h1 = hrow[lane + 32];
    const float* a = att + wid * (2 * RR);
    float ssrc = h0 * a[lane]      + h1 * a[lane + 32];
    float sdst = h0 * a[64 + lane] + h1 * a[96 + lane];
    #pragma unroll
    for (int d = 16; d; d >>= 1) {
        ssrc += __shfl_xor_sync(0xffffffffu, ssrc, d);
        sdst += __shfl_xor_sync(0xffffffffu, sdst, d);
    }
    if (lane == 0) {
        g_asrc[wid * NN + n] = ssrc;
        g_adst[wid * NN + n] = sdst;
    }
}

// ---------------------------------------------------------------------------
// Kernel 3: fused sparse GAT attention + aggregation, one block per row i.
// 512 threads: tid -> (h = tid>>6, r = tid&63). Deterministic compaction
// (warp scan + block scan, no atomics). Online softmax over 256-nbr chunks.
// ---------------------------------------------------------------------------
#define CHUNK 256
__global__ __launch_bounds__(512) void gat_row_kernel(
    const float* __restrict__ adj,
    const float* __restrict__ bias,
    float* __restrict__ out)
{
    __shared__ int   s_nbr[NN];            // 16 KB, worst case
    __shared__ float s_p[HH * CHUNK];      // 8 KB
    __shared__ float s_m[HH], s_l[HH], s_scale[HH], s_asrc[HH];
    __shared__ unsigned s_wsum[16], s_woff[16];
    __shared__ int s_L;

    const int i   = blockIdx.x;
    const int tid = threadIdx.x;
    const int wid = tid >> 5;
    const int lane = tid & 31;
    const int h = tid >> 6;
    const int r = tid & 63;

    // ---- Phase A: ordered neighbor-list compaction (8 contiguous cols/thread)
    const float* adjRow = adj + (size_t)i * NN;
    const int base = tid * 8;
    float4 v0 = *reinterpret_cast<const float4*>(adjRow + base);
    float4 v1 = *reinterpret_cast<const float4*>(adjRow + base + 4);
    unsigned mask = 0;
    mask |= (v0.x != 0.f) ? 1u   : 0u;
    mask |= (v0.y != 0.f) ? 2u   : 0u;
    mask |= (v0.z != 0.f) ? 4u   : 0u;
    mask |= (v0.w != 0.f) ? 8u   : 0u;
    mask |= (v1.x != 0.f) ? 16u  : 0u;
    mask |= (v1.y != 0.f) ? 32u  : 0u;
    mask |= (v1.z != 0.f) ? 64u  : 0u;
    mask |= (v1.w != 0.f) ? 128u : 0u;
    unsigned cnt_t = __popc(mask);

    unsigned inc = cnt_t;
    #pragma unroll
    for (int d = 1; d < 32; d <<= 1) {
        unsigned o = __shfl_up_sync(0xffffffffu, inc, d);
        if (lane >= d) inc += o;
    }
    if (lane == 31) s_wsum[wid] = inc;

    if (tid < 8) { s_m[tid] = -INFINITY; s_l[tid] = 0.f;
                   s_asrc[tid] = g_asrc[tid * NN + i]; }
    __syncthreads();

    if (tid < 32) {
        unsigned v = (tid < 16) ? s_wsum[tid] : 0u;
        unsigned in2 = v;
        #pragma unroll
        for (int d = 1; d < 16; d <<= 1) {
            unsigned o = __shfl_up_sync(0xffffffffu, in2, d);
            if (lane >= d) in2 += o;
        }
        if (tid < 16) s_woff[tid] = in2 - v;
        if (tid == 15) s_L = (int)in2;
    }
    __syncthreads();

    {
        int off = (int)(s_woff[wid] + (inc - cnt_t));
        unsigned m = mask;
        while (m) {
            int q = __ffs(m) - 1;
            s_nbr[off++] = base + q;
            m &= m - 1;
        }
    }
    __syncthreads();

    const int L = s_L;
    const float a_i = s_asrc[h];
    const size_t ibase = (size_t)i * NN;
    float acc = 0.f;

    // ---- Phase B: online softmax + aggregation over chunks
    for (int c0 = 0; c0 < L; c0 += CHUNK) {
        const int cnt = min(CHUNK, L - c0);
        // scores for all (head, kk) pairs
        #pragma unroll
        for (int q = 0; q < 4; q++) {
            int idx = tid + q * 512;        // 0..2047 ; hh = idx>>8, kk = idx&255
            int kk = idx & (CHUNK - 1);
            int hh = idx >> 8;
            float val = -1e30f;
            if (kk < cnt) {
                int j = s_nbr[c0 + kk];
                float pre = s_asrc[hh] + g_adst[hh * NN + j]
                          + EPSB * __ldg(bias + ibase + j);
                val = (pre >= 0.f) ? pre : ALPHA * pre;
            }
            s_p[idx] = val;
        }
        __syncthreads();

        // per-head online-softmax update: warp w handles head w
        if (wid < HH) {
            const int hh = wid;
            float mloc = -1e30f;
            #pragma unroll
            for (int q = 0; q < 8; q++)
                mloc = fmaxf(mloc, s_p[hh * CHUNK + lane + q * 32]);
            #pragma unroll
            for (int d = 16; d; d >>= 1)
                mloc = fmaxf(mloc, __shfl_xor_sync(0xffffffffu, mloc, d));
            float m_old = s_m[hh];
            float m_new = fmaxf(m_old, mloc);
            float sloc = 0.f;
            #pragma unroll
            for (int q = 0; q < 8; q++) {
                int idx = hh * CHUNK + lane + q * 32;
                float e = expf(s_p[idx] - m_new);
                s_p[idx] = e;
                sloc += e;
            }
            #pragma unroll
            for (int d = 16; d; d >>= 1)
                sloc += __shfl_xor_sync(0xffffffffu, sloc, d);
            if (lane == 0) {
                float sc = expf(m_old - m_new);   // 0 on first chunk (m_old=-inf)
                s_scale[hh] = sc;
                s_l[hh] = s_l[hh] * sc + sloc;
                s_m[hh] = m_new;
            }
        }
        __syncthreads();

        acc *= s_scale[h];
        const float* ph = &s_p[h * CHUNK];
        const int hr_off = (h << 6) + r;
        for (int kk = 0; kk < cnt; kk++) {
            int j = s_nbr[c0 + kk];
            acc = fmaf(ph[kk], g_hidden[(size_t)j * HR + hr_off], acc);
        }
        __syncthreads();   // protect s_p / s_scale before next chunk
    }

    out[(size_t)i * HR + (h << 6) + r] = acc / s_l[h];
    (void)a_i;
}

// ---------------------------------------------------------------------------
extern "C" void kernel_launch(void* const* d_in, const int* in_sizes, int n_in,
                              void* d_out, int out_size)
{
    const float* node = (const float*)d_in[0];   // [4096,512]
    const float* adj  = (const float*)d_in[1];   // [4096,4096]
    const float* W    = (const float*)d_in[2];   // [8,512,64]
    const float* att  = (const float*)d_in[3];   // [8,128]
    const float* bias = (const float*)d_in[4];   // [4096,4096]
    float* out = (float*)d_out;                  // [4096,512]

    gemm_hidden_kernel<<<dim3(HR / 64, NN / 128), 256>>>(node, W);
    src_dst_kernel<<<NN, 256>>>(att);
    gat_row_kernel<<<NN, 512>>>(adj, bias, out);
}

// round 4
// speedup vs baseline: 1.1678x; 1.1678x over previous
#include <cuda_runtime.h>
#include <cuda_bf16.h>
#include <math.h>
#include <stdint.h>

#define NN 4096
#define FF 512
#define RR 64
#define HH 8
#define HR 512          // H*R
#define EPSB 0.01f
#define ALPHA 0.2f

// Scratch (device globals: allocation-free per harness rules)
__device__ float g_hidden[NN * HR];   // [n][h*64+r]  (8 MB)
__device__ float g_Wt[HR * FF];       // [h*64+r][f]  (1 MB) transposed W
__device__ float g_asrc[HH * NN];
__device__ float g_adst[HH * NN];

// ---------------------------------------------------------------------------
// helpers
// ---------------------------------------------------------------------------
static __device__ __forceinline__ uint32_t smem_u32(const void* p) {
    return (uint32_t)__cvta_generic_to_shared(p);
}
static __device__ __forceinline__ uint32_t f2tf32(float x) {
    uint32_t r; asm("cvt.rna.tf32.f32 %0, %1;" : "=r"(r) : "f"(x)); return r;
}
static __device__ __forceinline__ void cp_async16(uint32_t dst, const void* src) {
    asm volatile("cp.async.cg.shared.global [%0], [%1], 16;" :: "r"(dst), "l"(src));
}
static __device__ __forceinline__ void cp_commit() {
    asm volatile("cp.async.commit_group;" ::: "memory");
}
template <int N_>
static __device__ __forceinline__ void cp_wait() {
    asm volatile("cp.async.wait_group %0;" :: "n"(N_) : "memory");
}
// D += A*B  (m16n8k8 tf32, row.col)
static __device__ __forceinline__ void mma8(float* c, const uint32_t* a, const uint32_t* b) {
    asm volatile(
        "mma.sync.aligned.m16n8k8.row.col.f32.tf32.tf32.f32 "
        "{%0,%1,%2,%3}, {%4,%5,%6,%7}, {%8,%9}, {%0,%1,%2,%3};"
        : "+f"(c[0]), "+f"(c[1]), "+f"(c[2]), "+f"(c[3])
        : "r"(a[0]), "r"(a[1]), "r"(a[2]), "r"(a[3]), "r"(b[0]), "r"(b[1]));
}

// ---------------------------------------------------------------------------
// Kernel 0: transpose W[h][f][r] -> g_Wt[(h*64+r)][f]
// ---------------------------------------------------------------------------
__global__ __launch_bounds__(256) void transposeW_kernel(const float* __restrict__ W)
{
    __shared__ float t[32][33];
    const int h = blockIdx.z, f0 = blockIdx.x * 32, r0 = blockIdx.y * 32;
    const float* Wh = W + (size_t)h * FF * RR;
    #pragma unroll
    for (int i = 0; i < 32; i += 8)
        t[threadIdx.y + i][threadIdx.x] =
            Wh[(size_t)(f0 + threadIdx.y + i) * RR + r0 + threadIdx.x];
    __syncthreads();
    #pragma unroll
    for (int i = 0; i < 32; i += 8)
        g_Wt[(size_t)(h * RR + r0 + threadIdx.y + i) * FF + f0 + threadIdx.x] =
            t[threadIdx.x][threadIdx.y + i];
}

// ---------------------------------------------------------------------------
// Kernel 1: 3xTF32 mma.sync GEMM: g_hidden = node[4096x512] @ g_Wt^T
// BM=128 BN=64 BK=32, 256 thr (8 warps: warp_m=wid&3 -> 32 rows,
// warp_n=wid>>2 -> 32 cols). cp.async double buffer, 48KB dynamic smem.
// Swizzle: phys_k4 = (k4 + row%8) & 7  (conflict-free fragment LDS).
// ---------------------------------------------------------------------------
#define A_STAGE (128 * 32 * 4)       // 16 KB
#define B_STAGE (64 * 32 * 4)        // 8 KB
#define STAGE_BYTES (A_STAGE + B_STAGE)  // 24 KB; x2 = 48 KB
__global__ __launch_bounds__(256) void gemm_mma_kernel(const float* __restrict__ A)
{
    extern __shared__ char smem[];
    const int tid = threadIdx.x;
    const int wid = tid >> 5;
    const int lane = tid & 31;
    const int grp = lane >> 2;       // 0..7
    const int thr = lane & 3;        // 0..3
    const int warp_m = wid & 3;
    const int warp_n = wid >> 2;
    const int bm = blockIdx.y * 128;
    const int bn = blockIdx.x * 64;
    const float* Bt = g_Wt;

    const uint32_t sA[2] = { smem_u32(smem), smem_u32(smem + STAGE_BYTES) };
    const uint32_t sB[2] = { sA[0] + A_STAGE, sA[1] + A_STAGE };

    // cp.async prefetch of one chunk (k0 = c*32) into stage st
    auto prefetch = [&](int c, int st) {
        const int k0 = c * 32;
        #pragma unroll
        for (int q = 0; q < 4; q++) {                 // A: 1024 granules
            int idx = tid + q * 256;
            int m = idx >> 3, k4 = idx & 7;
            int phys = (k4 + (m & 7)) & 7;
            cp_async16(sA[st] + m * 128 + phys * 16,
                       A + (size_t)(bm + m) * FF + k0 + k4 * 4);
        }
        #pragma unroll
        for (int q = 0; q < 2; q++) {                 // B: 512 granules
            int idx = tid + q * 256;
            int n = idx >> 3, k4 = idx & 7;
            int phys = (k4 + (n & 7)) & 7;
            cp_async16(sB[st] + n * 128 + phys * 16,
                       Bt + (size_t)(bn + n) * FF + k0 + k4 * 4);
        }
        cp_commit();
    };

    float acc[2][4][4];
    #pragma unroll
    for (int mt = 0; mt < 2; mt++)
        #pragma unroll
        for (int nt = 0; nt < 4; nt++)
            #pragma unroll
            for (int v = 0; v < 4; v++) acc[mt][nt][v] = 0.f;

    // per-thread fragment base addresses (byte offsets within stage)
    // A rows used: r(mt, half8) = warp_m*32 + mt*16 + grp + half8*8
    uint32_t aRowBase[2][2]; int aRot[2][2];
    #pragma unroll
    for (int mt = 0; mt < 2; mt++)
        #pragma unroll
        for (int hf = 0; hf < 2; hf++) {
            int row = warp_m * 32 + mt * 16 + grp + hf * 8;
            aRowBase[mt][hf] = row * 128 + thr * 4;
            aRot[mt][hf] = row & 7;
        }
    uint32_t bRowBase[4]; int bRot[4];
    #pragma unroll
    for (int nt = 0; nt < 4; nt++) {
        int n = warp_n * 32 + nt * 8 + grp;
        bRowBase[nt] = n * 128 + thr * 4;
        bRot[nt] = n & 7;
    }

    prefetch(0, 0);

    #pragma unroll 1
    for (int c = 0; c < FF / 32; c++) {
        const int st = c & 1;
        if (c + 1 < FF / 32) { prefetch(c + 1, st ^ 1); cp_wait<1>(); }
        else                 { cp_wait<0>(); }
        __syncthreads();

        #pragma unroll
        for (int s = 0; s < 4; s++) {       // 4 x k8 steps
            // load + split A fragments
            uint32_t ahi[2][4], alo[2][4];
            #pragma unroll
            for (int mt = 0; mt < 2; mt++) {
                #pragma unroll
                for (int hf = 0; hf < 2; hf++) {
                    #pragma unroll
                    for (int kh = 0; kh < 2; kh++) {   // k = s*8+thr (+4)
                        float x = *(const float*)(size_t)0; (void)x;
                        uint32_t addr = sA[st] + aRowBase[mt][hf]
                                      + (uint32_t)(((2 * s + kh + aRot[mt][hf]) & 7) * 16);
                        float v;
                        asm volatile("ld.shared.f32 %0, [%1];" : "=f"(v) : "r"(addr));
                        int ridx = hf + 2 * kh;        // a0=row0k0, a1=row8k0, a2=row0k4, a3=row8k4
                        uint32_t h = f2tf32(v);
                        ahi[mt][ridx] = h;
                        alo[mt][ridx] = f2tf32(v - __uint_as_float(h));
                    }
                }
            }
            // load + split B fragments
            uint32_t bhi[4][2], blo[4][2];
            #pragma unroll
            for (int nt = 0; nt < 4; nt++) {
                #pragma unroll
                for (int kh = 0; kh < 2; kh++) {
                    uint32_t addr = sB[st] + bRowBase[nt]
                                  + (uint32_t)(((2 * s + kh + bRot[nt]) & 7) * 16);
                    float v;
                    asm volatile("ld.shared.f32 %0, [%1];" : "=f"(v) : "r"(addr));
                    uint32_t h = f2tf32(v);
                    bhi[nt][kh] = h;
                    blo[nt][kh] = f2tf32(v - __uint_as_float(h));
                }
            }
            // 3-term mma
            #pragma unroll
            for (int mt = 0; mt < 2; mt++)
                #pragma unroll
                for (int nt = 0; nt < 4; nt++) {
                    mma8(acc[mt][nt], ahi[mt], bhi[nt]);
                    mma8(acc[mt][nt], ahi[mt], blo[nt]);
                    mma8(acc[mt][nt], alo[mt], bhi[nt]);
                }
        }
        __syncthreads();
    }

    // epilogue: c0,c1 -> (row grp, col thr*2 / +1); c2,c3 -> row grp+8
    #pragma unroll
    for (int mt = 0; mt < 2; mt++) {
        #pragma unroll
        for (int nt = 0; nt < 4; nt++) {
            int row0 = bm + warp_m * 32 + mt * 16 + grp;
            int col  = bn + warp_n * 32 + nt * 8 + thr * 2;
            float2 lo = make_float2(acc[mt][nt][0], acc[mt][nt][1]);
            float2 hi = make_float2(acc[mt][nt][2], acc[mt][nt][3]);
            *reinterpret_cast<float2*>(&g_hidden[(size_t)row0 * HR + col]) = lo;
            *reinterpret_cast<float2*>(&g_hidden[(size_t)(row0 + 8) * HR + col]) = hi;
        }
    }
}

// ---------------------------------------------------------------------------
// Kernel 2: a_src / a_dst per (head, node)
// ---------------------------------------------------------------------------
__global__ __launch_bounds__(256) void src_dst_kernel(const float* __restrict__ att)
{
    const int n = blockIdx.x;
    const int wid = threadIdx.x >> 5;
    const int lane = threadIdx.x & 31;
    const float* hrow = g_hidden + (size_t)n * HR + wid * RR;
    float h0 = hrow[lane], h1 = hrow[lane + 32];
    const float* a = att + wid * (2 * RR);
    float ssrc = h0 * a[lane]      + h1 * a[lane + 32];
    float sdst = h0 * a[64 + lane] + h1 * a[96 + lane];
    #pragma unroll
    for (int d = 16; d; d >>= 1) {
        ssrc += __shfl_xor_sync(0xffffffffu, ssrc, d);
        sdst += __shfl_xor_sync(0xffffffffu, sdst, d);
    }
    if (lane == 0) {
        g_asrc[wid * NN + n] = ssrc;
        g_adst[wid * NN + n] = sdst;
    }
}

// ---------------------------------------------------------------------------
// Kernel 3: fused sparse GAT attention + aggregation, one block per row i.
// Scores bounded (|pre| <~ 12): softmax without max-subtraction is fp32-safe.
// ---------------------------------------------------------------------------
#define SCHUNK 256
__global__ __launch_bounds__(512) void gat_row_kernel(
    const float* __restrict__ adj,
    const float* __restrict__ bias,
    float* __restrict__ out)
{
    __shared__ int   s_nbr[NN];
    __shared__ float s_p[HH * SCHUNK];
    __shared__ float s_l[HH], s_asrc[HH];
    __shared__ unsigned s_wsum[16], s_woff[16];
    __shared__ int s_L;

    const int i   = blockIdx.x;
    const int tid = threadIdx.x;
    const int wid = tid >> 5;
    const int lane = tid & 31;
    const int h = tid >> 6;
    const int r = tid & 63;

    // Phase A: ordered neighbor compaction (deterministic, no atomics)
    const float* adjRow = adj + (size_t)i * NN;
    const int base = tid * 8;
    float4 v0 = *reinterpret_cast<const float4*>(adjRow + base);
    float4 v1 = *reinterpret_cast<const float4*>(adjRow + base + 4);
    unsigned mask = 0;
    mask |= (v0.x != 0.f) ? 1u   : 0u;
    mask |= (v0.y != 0.f) ? 2u   : 0u;
    mask |= (v0.z != 0.f) ? 4u   : 0u;
    mask |= (v0.w != 0.f) ? 8u   : 0u;
    mask |= (v1.x != 0.f) ? 16u  : 0u;
    mask |= (v1.y != 0.f) ? 32u  : 0u;
    mask |= (v1.z != 0.f) ? 64u  : 0u;
    mask |= (v1.w != 0.f) ? 128u : 0u;
    unsigned cnt_t = __popc(mask);

    unsigned inc = cnt_t;
    #pragma unroll
    for (int d = 1; d < 32; d <<= 1) {
        unsigned o = __shfl_up_sync(0xffffffffu, inc, d);
        if (lane >= d) inc += o;
    }
    if (lane == 31) s_wsum[wid] = inc;

    if (tid < 8) { s_l[tid] = 0.f; s_asrc[tid] = g_asrc[tid * NN + i]; }
    __syncthreads();

    if (tid < 32) {
        unsigned v = (tid < 16) ? s_wsum[tid] : 0u;
        unsigned in2 = v;
        #pragma unroll
        for (int d = 1; d < 16; d <<= 1) {
            unsigned o = __shfl_up_sync(0xffffffffu, in2, d);
            if (lane >= d) in2 += o;
        }
        if (tid < 16) s_woff[tid] = in2 - v;
        if (tid == 15) s_L = (int)in2;
    }
    __syncthreads();

    {
        int off = (int)(s_woff[wid] + (inc - cnt_t));
        unsigned m = mask;
        while (m) {
            int q = __ffs(m) - 1;
            s_nbr[off++] = base + q;
            m &= m - 1;
        }
    }
    __syncthreads();

    const int L = s_L;
    const size_t ibase = (size_t)i * NN;
    float acc = 0.f;

    for (int c0 = 0; c0 < L; c0 += SCHUNK) {
        const int cnt = min(SCHUNK, L - c0);
        #pragma unroll
        for (int q = 0; q < 4; q++) {
            int idx = tid + q * 512;          // hh = idx>>8, kk = idx&255
            int kk = idx & (SCHUNK - 1);
            int hh = idx >> 8;
            float p = 0.f;
            if (kk < cnt) {
                int j = s_nbr[c0 + kk];
                float pre = s_asrc[hh] + g_adst[hh * NN + j]
                          + EPSB * __ldg(bias + ibase + j);
                pre = (pre >= 0.f) ? pre : ALPHA * pre;
                p = expf(pre);
            }
            s_p[idx] = p;
        }
        __syncthreads();

        if (wid < HH) {
            float sloc = 0.f;
            #pragma unroll
            for (int q = 0; q < 8; q++)
                sloc += s_p[wid * SCHUNK + lane + q * 32];
            #pragma unroll
            for (int d = 16; d; d >>= 1)
                sloc += __shfl_xor_sync(0xffffffffu, sloc, d);
            if (lane == 0) s_l[wid] += sloc;
        }

        const float* ph = &s_p[h * SCHUNK];
        const int hr_off = (h << 6) + r;
        for (int kk = 0; kk < cnt; kk++) {
            int j = s_nbr[c0 + kk];
            acc = fmaf(ph[kk], g_hidden[(size_t)j * HR + hr_off], acc);
        }
        __syncthreads();
    }

    out[(size_t)i * HR + (h << 6) + r] = acc / s_l[h];
}

// ---------------------------------------------------------------------------
extern "C" void kernel_launch(void* const* d_in, const int* in_sizes, int n_in,
                              void* d_out, int out_size)
{
    const float* node = (const float*)d_in[0];   // [4096,512]
    const float* adj  = (const float*)d_in[1];   // [4096,4096]
    const float* W    = (const float*)d_in[2];   // [8,512,64]
    const float* att  = (const float*)d_in[3];   // [8,128]
    const float* bias = (const float*)d_in[4];   // [4096,4096]
    float* out = (float*)d_out;                  // [4096,512]

    transposeW_kernel<<<dim3(FF / 32, RR / 32, HH), dim3(32, 8)>>>(W);
    gemm_mma_kernel<<<dim3(HR / 64, NN / 128), 256, 2 * STAGE_BYTES>>>(node);
    src_dst_kernel<<<NN, 256>>>(att);
    gat_row_kernel<<<NN, 512>>>(adj, bias, out);
}

// round 6
// speedup vs baseline: 1.6578x; 1.4196x over previous
#include <cuda_runtime.h>
#include <cuda_fp16.h>
#include <math.h>
#include <stdint.h>

#define NN 4096
#define FF 512
#define RR 64
#define HH 8
#define HR 512          // H*R
#define EPSB 0.01f
#define ALPHA 0.2f

// ---------------------------------------------------------------------------
// Device scratch (allocation-free per harness rules)
// ---------------------------------------------------------------------------
__device__ __align__(16) float g_hidden[NN * HR];      // [n][h*64+r]  8 MB
__device__ __align__(16) float g_asrc[HH * NN];        // [h][n]
__device__ __align__(16) float g_adstT[NN * HH];       // [n][h]  (transposed)
// fp16 hi/lo operands in m16n8k16 fragment layout
__device__ uint4 g_Ahi[NN * FF / 8];   // 4 MB  (lane-major 16B blocks)
__device__ uint4 g_Alo[NN * FF / 8];   // 4 MB
__device__ uint2 g_Bhi[HR * FF / 4];   // 512 KB
__device__ uint2 g_Blo[HR * FF / 4];   // 512 KB

// ---------------------------------------------------------------------------
// helpers
// ---------------------------------------------------------------------------
static __device__ __forceinline__ void cpa16(void* dst, const void* src) {
    uint32_t d = (uint32_t)__cvta_generic_to_shared(dst);
    asm volatile("cp.async.cg.shared.global [%0], [%1], 16;" :: "r"(d), "l"(src));
}
static __device__ __forceinline__ void cp_commit() {
    asm volatile("cp.async.commit_group;" ::: "memory");
}
template <int N_>
static __device__ __forceinline__ void cp_wait() {
    asm volatile("cp.async.wait_group %0;" :: "n"(N_) : "memory");
}
// hi/lo fp16 split of a float2 -> packed half2 words
static __device__ __forceinline__ void split2(float x, float y,
                                              uint32_t& hi, uint32_t& lo) {
    __half2 h = __floats2half2_rn(x, y);
    float rx = x - __low2float(h);
    float ry = y - __high2float(h);
    __half2 l = __floats2half2_rn(rx, ry);
    hi = *reinterpret_cast<uint32_t*>(&h);
    lo = *reinterpret_cast<uint32_t*>(&l);
}
// D += A*B  (m16n8k16 f16, f32 acc)
static __device__ __forceinline__ void mma16(float* c, const uint32_t* a,
                                             const uint32_t* b) {
    asm volatile(
        "mma.sync.aligned.m16n8k16.row.col.f32.f16.f16.f32 "
        "{%0,%1,%2,%3}, {%4,%5,%6,%7}, {%8,%9}, {%0,%1,%2,%3};"
        : "+f"(c[0]), "+f"(c[1]), "+f"(c[2]), "+f"(c[3])
        : "r"(a[0]), "r"(a[1]), "r"(a[2]), "r"(a[3]), "r"(b[0]), "r"(b[1]));
}

// ---------------------------------------------------------------------------
// Kernel P1: split A (node matrix) into fp16 hi/lo, MMA-fragment layout.
// Fragment id t = (rt*32 + ks)*32 + lane; regs {a0,a1,a2,a3} =
// {(m=g,k=t2..t2+1),(m=g+8,k..),(m=g,k+8..),(m=g+8,k+8..)}
// ---------------------------------------------------------------------------
__global__ __launch_bounds__(256) void preA_kernel(const float* __restrict__ A)
{
    int t = blockIdx.x * 256 + threadIdx.x;      // 262144 total
    int rt = t >> 10, ks = (t >> 5) & 31, ln = t & 31;
    int g = ln >> 2, tr = ln & 3;
    const float* p0 = A + (size_t)(rt * 16 + g) * FF + ks * 16 + tr * 2;
    float2 r0a = *reinterpret_cast<const float2*>(p0);
    float2 r0b = *reinterpret_cast<const float2*>(p0 + 8);
    float2 r1a = *reinterpret_cast<const float2*>(p0 + 8 * FF);
    float2 r1b = *reinterpret_cast<const float2*>(p0 + 8 * FF + 8);
    uint4 hv, lv;
    split2(r0a.x, r0a.y, hv.x, lv.x);
    split2(r1a.x, r1a.y, hv.y, lv.y);
    split2(r0b.x, r0b.y, hv.z, lv.z);
    split2(r1b.x, r1b.y, hv.w, lv.w);
    g_Ahi[t] = hv;
    g_Alo[t] = lv;
}

// ---------------------------------------------------------------------------
// Kernel P2: split + transpose W[h][f][r] -> B fragments (n = h*64+r, k = f).
// Fragment id t = (n8t*32 + ks)*32 + lane; regs {b0,b1} =
// {(k=t2..t2+1, n=g), (k+8..k+9, n=g)}
// ---------------------------------------------------------------------------
__global__ __launch_bounds__(256) void preB_kernel(const float* __restrict__ W)
{
    int t = blockIdx.x * 256 + threadIdx.x;      // 65536 total
    int n8 = t >> 10, ks = (t >> 5) & 31, ln = t & 31;
    int n = n8 * 8 + (ln >> 2);
    int k0 = ks * 16 + (ln & 3) * 2;
    int h = n >> 6, r = n & 63;
    const float* Wp = W + (size_t)h * FF * RR + (size_t)k0 * RR + r;
    float w00 = Wp[0], w01 = Wp[RR], w10 = Wp[8 * RR], w11 = Wp[9 * RR];
    uint2 hv, lv;
    split2(w00, w01, hv.x, lv.x);
    split2(w10, w11, hv.y, lv.y);
    g_Bhi[t] = hv;
    g_Blo[t] = lv;
}

// ---------------------------------------------------------------------------
// Kernel 1: 3xFP16 mma.sync GEMM: g_hidden = node @ W  (per-head concat)
// BM=128 BN=128 BK=32 (2 x k16), 256 thr: warp_m = wid&3 (32 rows),
// warp_n = wid>>2 (64 cols: 8 n8-tiles). cp.async double buffer, 64 KB smem.
// Stage layout: [Ahi 8K][Alo 8K][Bhi 8K][Blo 8K].
// ---------------------------------------------------------------------------
#define STAGE 32768
__global__ __launch_bounds__(256, 1) void gemm_mma_kernel()
{
    extern __shared__ char sm[];
    const int tid = threadIdx.x;
    const int wid = tid >> 5;
    const int lane = tid & 31;
    const int grp = lane >> 2;
    const int thr = lane & 3;
    const int warp_m = wid & 3;
    const int warp_n = wid >> 2;
    const int bm = blockIdx.y * 128;
    const int bn = blockIdx.x * 128;
    const int rtg0 = bm >> 4;      // global 16-row tile base
    const int n8g0 = bn >> 3;      // global n8 tile base

    auto prefetch = [&](int c, int st) {
        char* sa = sm + st * STAGE;
        #pragma unroll
        for (int q = 0; q < 2; q++) {
            int gidx = tid + q * 256;                   // 0..511
            int rt_l = gidx >> 6, ks_l = (gidx >> 5) & 1, ln2 = gidx & 31;
            size_t src = (size_t)(((rtg0 + rt_l) * 32) + (2 * c + ks_l)) * 32 + ln2;
            cpa16(sa + gidx * 16,        &g_Ahi[src]);
            cpa16(sa + 8192 + gidx * 16, &g_Alo[src]);
        }
        #pragma unroll
        for (int q = 0; q < 2; q++) {
            int gidx = tid + q * 256;
            int n8_l = gidx >> 5, ks_l = (gidx >> 4) & 1, lp = gidx & 15;
            // element index into uint2 arrays; 2*lp is even -> 16B aligned
            size_t src = (size_t)(((n8g0 + n8_l) * 32) + (2 * c + ks_l)) * 32 + 2 * lp;
            cpa16(sa + 16384 + gidx * 16, &g_Bhi[src]);
            cpa16(sa + 24576 + gidx * 16, &g_Blo[src]);
        }
        cp_commit();
    };

    float acc[2][8][4];
    #pragma unroll
    for (int mt = 0; mt < 2; mt++)
        #pragma unroll
        for (int nt = 0; nt < 8; nt++)
            #pragma unroll
            for (int v = 0; v < 4; v++) acc[mt][nt][v] = 0.f;

    prefetch(0, 0);

    #pragma unroll 1
    for (int c = 0; c < FF / 32; c++) {
        const int st = c & 1;
        if (c + 1 < FF / 32) { prefetch(c + 1, st ^ 1); cp_wait<1>(); }
        else                 { cp_wait<0>(); }
        __syncthreads();

        char* sa = sm + st * STAGE;
        #pragma unroll
        for (int ks = 0; ks < 2; ks++) {
            uint32_t bh[8][2], bl[8][2];
            #pragma unroll
            for (int nt = 0; nt < 8; nt++) {
                uint32_t off = (((warp_n * 8 + nt) * 2 + ks) * 32 + lane) * 8;
                uint2 vh = *reinterpret_cast<const uint2*>(sa + 16384 + off);
                uint2 vl = *reinterpret_cast<const uint2*>(sa + 24576 + off);
                bh[nt][0] = vh.x; bh[nt][1] = vh.y;
                bl[nt][0] = vl.x; bl[nt][1] = vl.y;
            }
            #pragma unroll
            for (int mt = 0; mt < 2; mt++) {
                uint32_t aoff = (((warp_m * 2 + mt) * 2 + ks) * 32 + lane) * 16;
                uint4 ah4 = *reinterpret_cast<const uint4*>(sa + aoff);
                uint4 al4 = *reinterpret_cast<const uint4*>(sa + 8192 + aoff);
                uint32_t ah[4] = {ah4.x, ah4.y, ah4.z, ah4.w};
                uint32_t al[4] = {al4.x, al4.y, al4.z, al4.w};
                #pragma unroll
                for (int nt = 0; nt < 8; nt++) {
                    mma16(acc[mt][nt], ah, bh[nt]);
                    mma16(acc[mt][nt], ah, bl[nt]);
                    mma16(acc[mt][nt], al, bh[nt]);
                }
            }
        }
        __syncthreads();
    }

    #pragma unroll
    for (int mt = 0; mt < 2; mt++) {
        #pragma unroll
        for (int nt = 0; nt < 8; nt++) {
            int row0 = bm + warp_m * 32 + mt * 16 + grp;
            int col  = bn + warp_n * 64 + nt * 8 + thr * 2;
            *reinterpret_cast<float2*>(&g_hidden[(size_t)row0 * HR + col]) =
                make_float2(acc[mt][nt][0], acc[mt][nt][1]);
            *reinterpret_cast<float2*>(&g_hidden[(size_t)(row0 + 8) * HR + col]) =
                make_float2(acc[mt][nt][2], acc[mt][nt][3]);
        }
    }
}

// ---------------------------------------------------------------------------
// Kernel 2: a_src[h][n], a_dstT[n][h]
// ---------------------------------------------------------------------------
__global__ __launch_bounds__(256) void src_dst_kernel(const float* __restrict__ att)
{
    const int n = blockIdx.x;
    const int wid = threadIdx.x >> 5;
    const int lane = threadIdx.x & 31;
    const float* hrow = g_hidden + (size_t)n * HR + wid * RR;
    float h0 = hrow[lane], h1 = hrow[lane + 32];
    const float* a = att + wid * (2 * RR);
    float ssrc = h0 * a[lane]      + h1 * a[lane + 32];
    float sdst = h0 * a[64 + lane] + h1 * a[96 + lane];
    #pragma unroll
    for (int d = 16; d; d >>= 1) {
        ssrc += __shfl_xor_sync(0xffffffffu, ssrc, d);
        sdst += __shfl_xor_sync(0xffffffffu, sdst, d);
    }
    if (lane == 0) {
        g_asrc[wid * NN + n] = ssrc;
        g_adstT[n * HH + wid] = sdst;
    }
}

// ---------------------------------------------------------------------------
// Kernel 3: fused sparse GAT attention + aggregation, one block per row i.
// Score phase: thread = (kk, head-group of 4): 1 bias LDG + 1 float4 adstT LDG
// per 4 heads. Aggregation: float4 per thread, 4 neighbor subsets, smem reduce.
// ---------------------------------------------------------------------------
#define SCHUNK 256
__global__ __launch_bounds__(512) void gat_row_kernel(
    const float* __restrict__ adj,
    const float* __restrict__ bias,
    float* __restrict__ out)
{
    __shared__ int   s_nbr[NN];            // 16 KB
    __shared__ __align__(16) float s_p[HH * SCHUNK];   // 8 KB (reused as reduce scratch)
    __shared__ float s_l[HH], s_asrc[HH];
    __shared__ unsigned s_wsum[16], s_woff[16];
    __shared__ int s_L;

    const int i   = blockIdx.x;
    const int tid = threadIdx.x;
    const int wid = tid >> 5;
    const int lane = tid & 31;

    // Phase A: ordered neighbor compaction (deterministic, no atomics)
    const float* adjRow = adj + (size_t)i * NN;
    const int base = tid * 8;
    float4 v0 = *reinterpret_cast<const float4*>(adjRow + base);
    float4 v1 = *reinterpret_cast<const float4*>(adjRow + base + 4);
    unsigned mask = 0;
    mask |= (v0.x != 0.f) ? 1u   : 0u;
    mask |= (v0.y != 0.f) ? 2u   : 0u;
    mask |= (v0.z != 0.f) ? 4u   : 0u;
    mask |= (v0.w != 0.f) ? 8u   : 0u;
    mask |= (v1.x != 0.f) ? 16u  : 0u;
    mask |= (v1.y != 0.f) ? 32u  : 0u;
    mask |= (v1.z != 0.f) ? 64u  : 0u;
    mask |= (v1.w != 0.f) ? 128u : 0u;
    unsigned cnt_t = __popc(mask);

    unsigned inc = cnt_t;
    #pragma unroll
    for (int d = 1; d < 32; d <<= 1) {
        unsigned o = __shfl_up_sync(0xffffffffu, inc, d);
        if (lane >= d) inc += o;
    }
    if (lane == 31) s_wsum[wid] = inc;

    if (tid < 8) { s_l[tid] = 0.f; s_asrc[tid] = g_asrc[tid * NN + i]; }
    __syncthreads();

    if (tid < 32) {
        unsigned v = (tid < 16) ? s_wsum[tid] : 0u;
        unsigned in2 = v;
        #pragma unroll
        for (int d = 1; d < 16; d <<= 1) {
            unsigned o = __shfl_up_sync(0xffffffffu, in2, d);
            if (lane >= d) in2 += o;
        }
        if (tid < 16) s_woff[tid] = in2 - v;
        if (tid == 15) s_L = (int)in2;
    }
    __syncthreads();

    {
        int off = (int)(s_woff[wid] + (inc - cnt_t));
        unsigned m = mask;
        while (m) {
            int q = __ffs(m) - 1;
            s_nbr[off++] = base + q;
            m &= m - 1;
        }
    }
    __syncthreads();

    const int L = s_L;
    const size_t ibase = (size_t)i * NN;
    const int sub  = tid >> 7;         // 0..3 neighbor subset
    const int hr4  = tid & 127;        // float4 column of g_hidden
    const int hAgg = hr4 >> 4;         // head for aggregation
    float4 a4 = make_float4(0.f, 0.f, 0.f, 0.f);

    for (int c0 = 0; c0 < L; c0 += SCHUNK) {
        const int cnt = min(SCHUNK, L - c0);
        // score phase: kk = tid&255, head group hg = tid>>8 (4 heads each)
        {
            const int kk = tid & 255;
            const int hg = tid >> 8;
            if (kk < cnt) {
                int j = s_nbr[c0 + kk];
                float4 ad = *reinterpret_cast<const float4*>(g_adstT + j * HH + hg * 4);
                float b = EPSB * __ldg(bias + ibase + j);
                const float* adp = &ad.x;
                #pragma unroll
                for (int q = 0; q < 4; q++) {
                    int hh = hg * 4 + q;
                    float pre = s_asrc[hh] + adp[q] + b;
                    pre = (pre >= 0.f) ? pre : ALPHA * pre;
                    s_p[hh * SCHUNK + kk] = __expf(pre);
                }
            } else {
                #pragma unroll
                for (int q = 0; q < 4; q++)
                    s_p[(hg * 4 + q) * SCHUNK + kk] = 0.f;
            }
        }
        __syncthreads();

        // per-head sum (warps 0-7) — runs alongside aggregation
        if (wid < HH) {
            float sloc = 0.f;
            #pragma unroll
            for (int q = 0; q < 8; q++)
                sloc += s_p[wid * SCHUNK + lane + q * 32];
            #pragma unroll
            for (int d = 16; d; d >>= 1)
                sloc += __shfl_xor_sync(0xffffffffu, sloc, d);
            if (lane == 0) s_l[wid] += sloc;
        }

        // aggregation: float4 per thread over neighbor subset
        const float* ph = &s_p[hAgg * SCHUNK];
        #pragma unroll 2
        for (int kk = sub; kk < cnt; kk += 4) {
            int j = s_nbr[c0 + kk];
            float p = ph[kk];
            float4 hv = *reinterpret_cast<const float4*>(
                g_hidden + (size_t)j * HR + hr4 * 4);
            a4.x = fmaf(p, hv.x, a4.x);
            a4.y = fmaf(p, hv.y, a4.y);
            a4.z = fmaf(p, hv.z, a4.z);
            a4.w = fmaf(p, hv.w, a4.w);
        }
        __syncthreads();
    }

    // cross-subset reduction via s_p scratch (4 x 128 float4 = 8 KB)
    float4* red = reinterpret_cast<float4*>(s_p);
    red[sub * 128 + hr4] = a4;
    __syncthreads();
    if (tid < 128) {
        float4 r0 = red[tid], r1 = red[128 + tid],
               r2 = red[256 + tid], r3 = red[384 + tid];
        float invl = 1.f / s_l[tid >> 4];
        float4 o;
        o.x = (r0.x + r1.x + r2.x + r3.x) * invl;
        o.y = (r0.y + r1.y + r2.y + r3.y) * invl;
        o.z = (r0.z + r1.z + r2.z + r3.z) * invl;
        o.w = (r0.w + r1.w + r2.w + r3.w) * invl;
        *reinterpret_cast<float4*>(out + (size_t)i * HR + tid * 4) = o;
    }
}

// ---------------------------------------------------------------------------
extern "C" void kernel_launch(void* const* d_in, const int* in_sizes, int n_in,
                              void* d_out, int out_size)
{
    const float* node = (const float*)d_in[0];   // [4096,512]
    const float* adj  = (const float*)d_in[1];   // [4096,4096]
    const float* W    = (const float*)d_in[2];   // [8,512,64]
    const float* att  = (const float*)d_in[3];   // [8,128]
    const float* bias = (const float*)d_in[4];   // [4096,4096]
    float* out = (float*)d_out;                  // [4096,512]

    cudaFuncSetAttribute(gemm_mma_kernel,
                         cudaFuncAttributeMaxDynamicSharedMemorySize, 2 * STAGE);

    preA_kernel<<<NN * FF / 8 / 256, 256>>>(node);
    preB_kernel<<<HR * FF / 4 / 256, 256>>>(W);
    gemm_mma_kernel<<<dim3(HR / 128, NN / 128), 256, 2 * STAGE>>>();
    src_dst_kernel<<<NN, 256>>>(att);
    gat_row_kernel<<<NN, 512>>>(adj, bias, out);
}

// round 7
// speedup vs baseline: 1.8216x; 1.0988x over previous
#include <cuda_runtime.h>
#include <cuda_fp16.h>
#include <math.h>
#include <stdint.h>

#define NN 4096
#define FF 512
#define RR 64
#define HH 8
#define HR 512          // H*R
#define EPSB 0.01f
#define ALPHA 0.2f

// ---------------------------------------------------------------------------
// Device scratch (allocation-free per harness rules)
// ---------------------------------------------------------------------------
__device__ __align__(16) __half g_hidden_h[NN * HR];   // [n][h*64+r] fp16, 4 MB
__device__ __align__(16) float g_asrc[HH * NN];        // [h][n]
__device__ __align__(16) float g_adstT[NN * HH];       // [n][h]
// fp16 hi/lo GEMM operands in m16n8k16 fragment layout
__device__ uint4 g_Ahi[NN * FF / 8];   // 4 MB
__device__ uint4 g_Alo[NN * FF / 8];   // 4 MB
__device__ uint2 g_Bhi[HR * FF / 4];   // 512 KB
__device__ uint2 g_Blo[HR * FF / 4];   // 512 KB

// ---------------------------------------------------------------------------
// helpers
// ---------------------------------------------------------------------------
static __device__ __forceinline__ void cpa16(void* dst, const void* src) {
    uint32_t d = (uint32_t)__cvta_generic_to_shared(dst);
    asm volatile("cp.async.cg.shared.global [%0], [%1], 16;" :: "r"(d), "l"(src));
}
static __device__ __forceinline__ void cp_commit() {
    asm volatile("cp.async.commit_group;" ::: "memory");
}
template <int N_>
static __device__ __forceinline__ void cp_wait() {
    asm volatile("cp.async.wait_group %0;" :: "n"(N_) : "memory");
}
static __device__ __forceinline__ void split2(float x, float y,
                                              uint32_t& hi, uint32_t& lo) {
    __half2 h = __floats2half2_rn(x, y);
    float rx = x - __low2float(h);
    float ry = y - __high2float(h);
    __half2 l = __floats2half2_rn(rx, ry);
    hi = *reinterpret_cast<uint32_t*>(&h);
    lo = *reinterpret_cast<uint32_t*>(&l);
}
static __device__ __forceinline__ void mma16(float* c, const uint32_t* a,
                                             const uint32_t* b) {
    asm volatile(
        "mma.sync.aligned.m16n8k16.row.col.f32.f16.f16.f32 "
        "{%0,%1,%2,%3}, {%4,%5,%6,%7}, {%8,%9}, {%0,%1,%2,%3};"
        : "+f"(c[0]), "+f"(c[1]), "+f"(c[2]), "+f"(c[3])
        : "r"(a[0]), "r"(a[1]), "r"(a[2]), "r"(a[3]), "r"(b[0]), "r"(b[1]));
}

// ---------------------------------------------------------------------------
// Kernel P1: split A (node matrix) into fp16 hi/lo, MMA-fragment layout.
// ---------------------------------------------------------------------------
__global__ __launch_bounds__(256) void preA_kernel(const float* __restrict__ A)
{
    int t = blockIdx.x * 256 + threadIdx.x;      // 262144 total
    int rt = t >> 10, ks = (t >> 5) & 31, ln = t & 31;
    int g = ln >> 2, tr = ln & 3;
    const float* p0 = A + (size_t)(rt * 16 + g) * FF + ks * 16 + tr * 2;
    float2 r0a = *reinterpret_cast<const float2*>(p0);
    float2 r0b = *reinterpret_cast<const float2*>(p0 + 8);
    float2 r1a = *reinterpret_cast<const float2*>(p0 + 8 * FF);
    float2 r1b = *reinterpret_cast<const float2*>(p0 + 8 * FF + 8);
    uint4 hv, lv;
    split2(r0a.x, r0a.y, hv.x, lv.x);
    split2(r1a.x, r1a.y, hv.y, lv.y);
    split2(r0b.x, r0b.y, hv.z, lv.z);
    split2(r1b.x, r1b.y, hv.w, lv.w);
    g_Ahi[t] = hv;
    g_Alo[t] = lv;
}

// ---------------------------------------------------------------------------
// Kernel P2: split + transpose W[h][f][r] -> B fragments (n = h*64+r, k = f).
// ---------------------------------------------------------------------------
__global__ __launch_bounds__(256) void preB_kernel(const float* __restrict__ W)
{
    int t = blockIdx.x * 256 + threadIdx.x;      // 65536 total
    int n8 = t >> 10, ks = (t >> 5) & 31, ln = t & 31;
    int n = n8 * 8 + (ln >> 2);
    int k0 = ks * 16 + (ln & 3) * 2;
    int h = n >> 6, r = n & 63;
    const float* Wp = W + (size_t)h * FF * RR + (size_t)k0 * RR + r;
    float w00 = Wp[0], w01 = Wp[RR], w10 = Wp[8 * RR], w11 = Wp[9 * RR];
    uint2 hv, lv;
    split2(w00, w01, hv.x, lv.x);
    split2(w10, w11, hv.y, lv.y);
    g_Bhi[t] = hv;
    g_Blo[t] = lv;
}

// ---------------------------------------------------------------------------
// Kernel 1: 3xFP16 mma.sync GEMM + fused epilogue:
//   - writes hidden as fp16 (g_hidden_h)
//   - computes a_src/a_dst per (row, head) from fp32 accumulators
// BM=128 BN=128 BK=32, 256 thr. warp_n owns one full head (64 cols).
// ---------------------------------------------------------------------------
#define STAGE 32768
__global__ __launch_bounds__(256, 1) void gemm_mma_kernel(const float* __restrict__ att)
{
    extern __shared__ char sm[];
    const int tid = threadIdx.x;
    const int lane = tid & 31;
    const int wid = tid >> 5;
    const int grp = lane >> 2;
    const int thr = lane & 3;
    const int warp_m = wid & 3;
    const int warp_n = wid >> 2;
    const int bm = blockIdx.y * 128;
    const int bn = blockIdx.x * 128;
    const int rtg0 = bm >> 4;
    const int n8g0 = bn >> 3;

    auto prefetch = [&](int c, int st) {
        char* sa = sm + st * STAGE;
        #pragma unroll
        for (int q = 0; q < 2; q++) {
            int gidx = tid + q * 256;
            int rt_l = gidx >> 6, ks_l = (gidx >> 5) & 1, ln2 = gidx & 31;
            size_t src = (size_t)(((rtg0 + rt_l) * 32) + (2 * c + ks_l)) * 32 + ln2;
            cpa16(sa + gidx * 16,        &g_Ahi[src]);
            cpa16(sa + 8192 + gidx * 16, &g_Alo[src]);
        }
        #pragma unroll
        for (int q = 0; q < 2; q++) {
            int gidx = tid + q * 256;
            int n8_l = gidx >> 5, ks_l = (gidx >> 4) & 1, lp = gidx & 15;
            size_t src = (size_t)(((n8g0 + n8_l) * 32) + (2 * c + ks_l)) * 32 + 2 * lp;
            cpa16(sa + 16384 + gidx * 16, &g_Bhi[src]);
            cpa16(sa + 24576 + gidx * 16, &g_Blo[src]);
        }
        cp_commit();
    };

    float acc[2][8][4];
    #pragma unroll
    for (int mt = 0; mt < 2; mt++)
        #pragma unroll
        for (int nt = 0; nt < 8; nt++)
            #pragma unroll
            for (int v = 0; v < 4; v++) acc[mt][nt][v] = 0.f;

    prefetch(0, 0);

    #pragma unroll 1
    for (int c = 0; c < FF / 32; c++) {
        const int st = c & 1;
        if (c + 1 < FF / 32) { prefetch(c + 1, st ^ 1); cp_wait<1>(); }
        else                 { cp_wait<0>(); }
        __syncthreads();

        char* sa = sm + st * STAGE;
        #pragma unroll
        for (int ks = 0; ks < 2; ks++) {
            uint32_t bh[8][2], bl[8][2];
            #pragma unroll
            for (int nt = 0; nt < 8; nt++) {
                uint32_t off = (((warp_n * 8 + nt) * 2 + ks) * 32 + lane) * 8;
                uint2 vh = *reinterpret_cast<const uint2*>(sa + 16384 + off);
                uint2 vl = *reinterpret_cast<const uint2*>(sa + 24576 + off);
                bh[nt][0] = vh.x; bh[nt][1] = vh.y;
                bl[nt][0] = vl.x; bl[nt][1] = vl.y;
            }
            #pragma unroll
            for (int mt = 0; mt < 2; mt++) {
                uint32_t aoff = (((warp_m * 2 + mt) * 2 + ks) * 32 + lane) * 16;
                uint4 ah4 = *reinterpret_cast<const uint4*>(sa + aoff);
                uint4 al4 = *reinterpret_cast<const uint4*>(sa + 8192 + aoff);
                uint32_t ah[4] = {ah4.x, ah4.y, ah4.z, ah4.w};
                uint32_t al[4] = {al4.x, al4.y, al4.z, al4.w};
                #pragma unroll
                for (int nt = 0; nt < 8; nt++) {
                    mma16(acc[mt][nt], ah, bh[nt]);
                    mma16(acc[mt][nt], ah, bl[nt]);
                    mma16(acc[mt][nt], al, bh[nt]);
                }
            }
        }
        __syncthreads();
    }

    // ---- epilogue ----
    const int h = blockIdx.x * 2 + warp_n;       // head owned by this warp
    // attention weights for this thread's 16 (nt, v) columns
    float wS0[8], wS1[8], wD0[8], wD1[8];
    #pragma unroll
    for (int nt = 0; nt < 8; nt++) {
        int r = nt * 8 + thr * 2;
        const float* ah = att + h * (2 * RR);
        wS0[nt] = ah[r];      wS1[nt] = ah[r + 1];
        wD0[nt] = ah[64 + r]; wD1[nt] = ah[64 + r + 1];
    }

    #pragma unroll
    for (int mt = 0; mt < 2; mt++) {
        float ssum[2] = {0.f, 0.f}, dsum[2] = {0.f, 0.f};
        #pragma unroll
        for (int nt = 0; nt < 8; nt++) {
            int row0 = bm + warp_m * 32 + mt * 16 + grp;
            int col  = bn + warp_n * 64 + nt * 8 + thr * 2;
            // fp16 hidden stores
            *reinterpret_cast<__half2*>(&g_hidden_h[(size_t)row0 * HR + col]) =
                __floats2half2_rn(acc[mt][nt][0], acc[mt][nt][1]);
            *reinterpret_cast<__half2*>(&g_hidden_h[(size_t)(row0 + 8) * HR + col]) =
                __floats2half2_rn(acc[mt][nt][2], acc[mt][nt][3]);
            // src/dst partials (hf=0: row0, hf=1: row0+8)
            ssum[0] = fmaf(acc[mt][nt][0], wS0[nt], fmaf(acc[mt][nt][1], wS1[nt], ssum[0]));
            dsum[0] = fmaf(acc[mt][nt][0], wD0[nt], fmaf(acc[mt][nt][1], wD1[nt], dsum[0]));
            ssum[1] = fmaf(acc[mt][nt][2], wS0[nt], fmaf(acc[mt][nt][3], wS1[nt], ssum[1]));
            dsum[1] = fmaf(acc[mt][nt][2], wD0[nt], fmaf(acc[mt][nt][3], wD1[nt], dsum[1]));
        }
        // reduce across the 4 thr lanes of this group
        #pragma unroll
        for (int hf = 0; hf < 2; hf++) {
            ssum[hf] += __shfl_xor_sync(0xffffffffu, ssum[hf], 1);
            ssum[hf] += __shfl_xor_sync(0xffffffffu, ssum[hf], 2);
            dsum[hf] += __shfl_xor_sync(0xffffffffu, dsum[hf], 1);
            dsum[hf] += __shfl_xor_sync(0xffffffffu, dsum[hf], 2);
        }
        if (thr == 0) {
            #pragma unroll
            for (int hf = 0; hf < 2; hf++) {
                int row = bm + warp_m * 32 + mt * 16 + grp + hf * 8;
                g_asrc[h * NN + row] = ssum[hf];
                g_adstT[row * HH + h] = dsum[hf];
            }
        }
    }
}

// ---------------------------------------------------------------------------
// Kernel 3: fused sparse GAT attention + aggregation, one block per row i.
// Aggregation gathers fp16 hidden (half4 per thread = 8B).
// ---------------------------------------------------------------------------
#define SCHUNK 256
__global__ __launch_bounds__(512) void gat_row_kernel(
    const float* __restrict__ adj,
    const float* __restrict__ bias,
    float* __restrict__ out)
{
    __shared__ int   s_nbr[NN];            // 16 KB
    __shared__ __align__(16) float s_p[HH * SCHUNK];   // 8 KB (also reduce scratch)
    __shared__ float s_l[HH], s_asrc[HH];
    __shared__ unsigned s_wsum[16], s_woff[16];
    __shared__ int s_L;

    const int i   = blockIdx.x;
    const int tid = threadIdx.x;
    const int wid = tid >> 5;
    const int lane = tid & 31;

    // Phase A: ordered neighbor compaction (deterministic, no atomics)
    const float* adjRow = adj + (size_t)i * NN;
    const int base = tid * 8;
    float4 v0 = *reinterpret_cast<const float4*>(adjRow + base);
    float4 v1 = *reinterpret_cast<const float4*>(adjRow + base + 4);
    unsigned mask = 0;
    mask |= (v0.x != 0.f) ? 1u   : 0u;
    mask |= (v0.y != 0.f) ? 2u   : 0u;
    mask |= (v0.z != 0.f) ? 4u   : 0u;
    mask |= (v0.w != 0.f) ? 8u   : 0u;
    mask |= (v1.x != 0.f) ? 16u  : 0u;
    mask |= (v1.y != 0.f) ? 32u  : 0u;
    mask |= (v1.z != 0.f) ? 64u  : 0u;
    mask |= (v1.w != 0.f) ? 128u : 0u;
    unsigned cnt_t = __popc(mask);

    unsigned inc = cnt_t;
    #pragma unroll
    for (int d = 1; d < 32; d <<= 1) {
        unsigned o = __shfl_up_sync(0xffffffffu, inc, d);
        if (lane >= d) inc += o;
    }
    if (lane == 31) s_wsum[wid] = inc;

    if (tid < 8) { s_l[tid] = 0.f; s_asrc[tid] = g_asrc[tid * NN + i]; }
    __syncthreads();

    if (tid < 32) {
        unsigned v = (tid < 16) ? s_wsum[tid] : 0u;
        unsigned in2 = v;
        #pragma unroll
        for (int d = 1; d < 16; d <<= 1) {
            unsigned o = __shfl_up_sync(0xffffffffu, in2, d);
            if (lane >= d) in2 += o;
        }
        if (tid < 16) s_woff[tid] = in2 - v;
        if (tid == 15) s_L = (int)in2;
    }
    __syncthreads();

    {
        int off = (int)(s_woff[wid] + (inc - cnt_t));
        unsigned m = mask;
        while (m) {
            int q = __ffs(m) - 1;
            s_nbr[off++] = base + q;
            m &= m - 1;
        }
    }
    __syncthreads();

    const int L = s_L;
    const size_t ibase = (size_t)i * NN;
    const int sub  = tid >> 7;         // 0..3 neighbor subset
    const int hr4  = tid & 127;        // 4-col group of hidden
    const int hAgg = hr4 >> 4;         // head for aggregation
    float4 a4 = make_float4(0.f, 0.f, 0.f, 0.f);

    for (int c0 = 0; c0 < L; c0 += SCHUNK) {
        const int cnt = min(SCHUNK, L - c0);
        // score phase: kk = tid&255, head group hg = tid>>8 (4 heads each)
        {
            const int kk = tid & 255;
            const int hg = tid >> 8;
            if (kk < cnt) {
                int j = s_nbr[c0 + kk];
                float4 ad = *reinterpret_cast<const float4*>(g_adstT + j * HH + hg * 4);
                float b = EPSB * __ldg(bias + ibase + j);
                const float* adp = &ad.x;
                #pragma unroll
                for (int q = 0; q < 4; q++) {
                    int hh = hg * 4 + q;
                    float pre = s_asrc[hh] + adp[q] + b;
                    pre = (pre >= 0.f) ? pre : ALPHA * pre;
                    s_p[hh * SCHUNK + kk] = __expf(pre);
                }
            } else {
                #pragma unroll
                for (int q = 0; q < 4; q++)
                    s_p[(hg * 4 + q) * SCHUNK + kk] = 0.f;
            }
        }
        __syncthreads();

        // per-head sum (warps 0-7) — runs alongside aggregation
        if (wid < HH) {
            float sloc = 0.f;
            #pragma unroll
            for (int q = 0; q < 8; q++)
                sloc += s_p[wid * SCHUNK + lane + q * 32];
            #pragma unroll
            for (int d = 16; d; d >>= 1)
                sloc += __shfl_xor_sync(0xffffffffu, sloc, d);
            if (lane == 0) s_l[wid] += sloc;
        }

        // aggregation: half4 per thread over neighbor subset
        const float* ph = &s_p[hAgg * SCHUNK];
        #pragma unroll 2
        for (int kk = sub; kk < cnt; kk += 4) {
            int j = s_nbr[c0 + kk];
            float p = ph[kk];
            uint2 u = *reinterpret_cast<const uint2*>(
                g_hidden_h + (size_t)j * HR + hr4 * 4);
            float2 f0 = __half22float2(*reinterpret_cast<__half2*>(&u.x));
            float2 f1 = __half22float2(*reinterpret_cast<__half2*>(&u.y));
            a4.x = fmaf(p, f0.x, a4.x);
            a4.y = fmaf(p, f0.y, a4.y);
            a4.z = fmaf(p, f1.x, a4.z);
            a4.w = fmaf(p, f1.y, a4.w);
        }
        __syncthreads();
    }

    // cross-subset reduction via s_p scratch (4 x 128 float4 = 8 KB)
    float4* red = reinterpret_cast<float4*>(s_p);
    red[sub * 128 + hr4] = a4;
    __syncthreads();
    if (tid < 128) {
        float4 r0 = red[tid], r1 = red[128 + tid],
               r2 = red[256 + tid], r3 = red[384 + tid];
        float invl = 1.f / s_l[tid >> 4];
        float4 o;
        o.x = (r0.x + r1.x + r2.x + r3.x) * invl;
        o.y = (r0.y + r1.y + r2.y + r3.y) * invl;
        o.z = (r0.z + r1.z + r2.z + r3.z) * invl;
        o.w = (r0.w + r1.w + r2.w + r3.w) * invl;
        *reinterpret_cast<float4*>(out + (size_t)i * HR + tid * 4) = o;
    }
}

// ---------------------------------------------------------------------------
extern "C" void kernel_launch(void* const* d_in, const int* in_sizes, int n_in,
                              void* d_out, int out_size)
{
    const float* node = (const float*)d_in[0];   // [4096,512]
    const float* adj  = (const float*)d_in[1];   // [4096,4096]
    const float* W    = (const float*)d_in[2];   // [8,512,64]
    const float* att  = (const float*)d_in[3];   // [8,128]
    const float* bias = (const float*)d_in[4];   // [4096,4096]
    float* out = (float*)d_out;                  // [4096,512]

    cudaFuncSetAttribute(gemm_mma_kernel,
                         cudaFuncAttributeMaxDynamicSharedMemorySize, 2 * STAGE);

    preA_kernel<<<NN * FF / 8 / 256, 256>>>(node);
    preB_kernel<<<HR * FF / 4 / 256, 256>>>(W);
    gemm_mma_kernel<<<dim3(HR / 128, NN / 128), 256, 2 * STAGE>>>(att);
    gat_row_kernel<<<NN, 512>>>(adj, bias, out);
}

// round 9
// speedup vs baseline: 1.8362x; 1.0080x over previous
// R9 = R8 resubmission (container infra failure x2, no defect found in audit)
#include <cuda_runtime.h>
#include <cuda_fp16.h>
#include <math.h>
#include <stdint.h>

#define NN 4096
#define FF 512
#define RR 64
#define HH 8
#define HR 512          // H*R
#define EPSB 0.01f
#define ALPHA 0.2f

// ---------------------------------------------------------------------------
// Device scratch (allocation-free per harness rules)
// ---------------------------------------------------------------------------
__device__ __align__(16) __half g_hidden_h[NN * HR];   // [n][h*64+r] fp16, 4 MB
__device__ __align__(16) float g_asrc[HH * NN];        // [h][n]
__device__ __align__(16) float g_adstT[NN * HH];       // [n][h]
// fp16 hi/lo GEMM operands in m16n8k16 fragment layout
__device__ uint4 g_Ahi[NN * FF / 8];   // 4 MB
__device__ uint4 g_Alo[NN * FF / 8];   // 4 MB
__device__ uint2 g_Bhi[HR * FF / 4];   // 512 KB
__device__ uint2 g_Blo[HR * FF / 4];   // 512 KB

// ---------------------------------------------------------------------------
// helpers
// ---------------------------------------------------------------------------
static __device__ __forceinline__ void cpa16(void* dst, const void* src) {
    uint32_t d = (uint32_t)__cvta_generic_to_shared(dst);
    asm volatile("cp.async.cg.shared.global [%0], [%1], 16;" :: "r"(d), "l"(src));
}
static __device__ __forceinline__ void cp_commit() {
    asm volatile("cp.async.commit_group;" ::: "memory");
}
template <int N_>
static __device__ __forceinline__ void cp_wait() {
    asm volatile("cp.async.wait_group %0;" :: "n"(N_) : "memory");
}
static __device__ __forceinline__ void split2(float x, float y,
                                              uint32_t& hi, uint32_t& lo) {
    __half2 h = __floats2half2_rn(x, y);
    float rx = x - __low2float(h);
    float ry = y - __high2float(h);
    __half2 l = __floats2half2_rn(rx, ry);
    hi = *reinterpret_cast<uint32_t*>(&h);
    lo = *reinterpret_cast<uint32_t*>(&l);
}
static __device__ __forceinline__ void mma16(float* c, const uint32_t* a,
                                             const uint32_t* b) {
    asm volatile(
        "mma.sync.aligned.m16n8k16.row.col.f32.f16.f16.f32 "
        "{%0,%1,%2,%3}, {%4,%5,%6,%7}, {%8,%9}, {%0,%1,%2,%3};"
        : "+f"(c[0]), "+f"(c[1]), "+f"(c[2]), "+f"(c[3])
        : "r"(a[0]), "r"(a[1]), "r"(a[2]), "r"(a[3]), "r"(b[0]), "r"(b[1]));
}

// ---------------------------------------------------------------------------
// Kernel P1: split A (node matrix) into fp16 hi/lo, MMA-fragment layout.
// ---------------------------------------------------------------------------
__global__ __launch_bounds__(256) void preA_kernel(const float* __restrict__ A)
{
    int t = blockIdx.x * 256 + threadIdx.x;      // 262144 total
    int rt = t >> 10, ks = (t >> 5) & 31, ln = t & 31;
    int g = ln >> 2, tr = ln & 3;
    const float* p0 = A + (size_t)(rt * 16 + g) * FF + ks * 16 + tr * 2;
    float2 r0a = *reinterpret_cast<const float2*>(p0);
    float2 r0b = *reinterpret_cast<const float2*>(p0 + 8);
    float2 r1a = *reinterpret_cast<const float2*>(p0 + 8 * FF);
    float2 r1b = *reinterpret_cast<const float2*>(p0 + 8 * FF + 8);
    uint4 hv, lv;
    split2(r0a.x, r0a.y, hv.x, lv.x);
    split2(r1a.x, r1a.y, hv.y, lv.y);
    split2(r0b.x, r0b.y, hv.z, lv.z);
    split2(r1b.x, r1b.y, hv.w, lv.w);
    g_Ahi[t] = hv;
    g_Alo[t] = lv;
}

// ---------------------------------------------------------------------------
// Kernel P2: split + transpose W[h][f][r] -> B fragments (n = h*64+r, k = f).
// ---------------------------------------------------------------------------
__global__ __launch_bounds__(256) void preB_kernel(const float* __restrict__ W)
{
    int t = blockIdx.x * 256 + threadIdx.x;      // 65536 total
    int n8 = t >> 10, ks = (t >> 5) & 31, ln = t & 31;
    int n = n8 * 8 + (ln >> 2);
    int k0 = ks * 16 + (ln & 3) * 2;
    int h = n >> 6, r = n & 63;
    const float* Wp = W + (size_t)h * FF * RR + (size_t)k0 * RR + r;
    float w00 = Wp[0], w01 = Wp[RR], w10 = Wp[8 * RR], w11 = Wp[9 * RR];
    uint2 hv, lv;
    split2(w00, w01, hv.x, lv.x);
    split2(w10, w11, hv.y, lv.y);
    g_Bhi[t] = hv;
    g_Blo[t] = lv;
}

// ---------------------------------------------------------------------------
// Kernel 1: 3xFP16 mma.sync GEMM + fused epilogue (fp16 hidden + src/dst)
// ---------------------------------------------------------------------------
#define STAGE 32768
__global__ __launch_bounds__(256, 1) void gemm_mma_kernel(const float* __restrict__ att)
{
    extern __shared__ char sm[];
    const int tid = threadIdx.x;
    const int lane = tid & 31;
    const int wid = tid >> 5;
    const int grp = lane >> 2;
    const int thr = lane & 3;
    const int warp_m = wid & 3;
    const int warp_n = wid >> 2;
    const int bm = blockIdx.y * 128;
    const int bn = blockIdx.x * 128;
    const int rtg0 = bm >> 4;
    const int n8g0 = bn >> 3;

    auto prefetch = [&](int c, int st) {
        char* sa = sm + st * STAGE;
        #pragma unroll
        for (int q = 0; q < 2; q++) {
            int gidx = tid + q * 256;
            int rt_l = gidx >> 6, ks_l = (gidx >> 5) & 1, ln2 = gidx & 31;
            size_t src = (size_t)(((rtg0 + rt_l) * 32) + (2 * c + ks_l)) * 32 + ln2;
            cpa16(sa + gidx * 16,        &g_Ahi[src]);
            cpa16(sa + 8192 + gidx * 16, &g_Alo[src]);
        }
        #pragma unroll
        for (int q = 0; q < 2; q++) {
            int gidx = tid + q * 256;
            int n8_l = gidx >> 5, ks_l = (gidx >> 4) & 1, lp = gidx & 15;
            size_t src = (size_t)(((n8g0 + n8_l) * 32) + (2 * c + ks_l)) * 32 + 2 * lp;
            cpa16(sa + 16384 + gidx * 16, &g_Bhi[src]);
            cpa16(sa + 24576 + gidx * 16, &g_Blo[src]);
        }
        cp_commit();
    };

    float acc[2][8][4];
    #pragma unroll
    for (int mt = 0; mt < 2; mt++)
        #pragma unroll
        for (int nt = 0; nt < 8; nt++)
            #pragma unroll
            for (int v = 0; v < 4; v++) acc[mt][nt][v] = 0.f;

    prefetch(0, 0);

    #pragma unroll 1
    for (int c = 0; c < FF / 32; c++) {
        const int st = c & 1;
        if (c + 1 < FF / 32) { prefetch(c + 1, st ^ 1); cp_wait<1>(); }
        else                 { cp_wait<0>(); }
        __syncthreads();

        char* sa = sm + st * STAGE;
        #pragma unroll
        for (int ks = 0; ks < 2; ks++) {
            uint32_t bh[8][2], bl[8][2];
            #pragma unroll
            for (int nt = 0; nt < 8; nt++) {
                uint32_t off = (((warp_n * 8 + nt) * 2 + ks) * 32 + lane) * 8;
                uint2 vh = *reinterpret_cast<const uint2*>(sa + 16384 + off);
                uint2 vl = *reinterpret_cast<const uint2*>(sa + 24576 + off);
                bh[nt][0] = vh.x; bh[nt][1] = vh.y;
                bl[nt][0] = vl.x; bl[nt][1] = vl.y;
            }
            #pragma unroll
            for (int mt = 0; mt < 2; mt++) {
                uint32_t aoff = (((warp_m * 2 + mt) * 2 + ks) * 32 + lane) * 16;
                uint4 ah4 = *reinterpret_cast<const uint4*>(sa + aoff);
                uint4 al4 = *reinterpret_cast<const uint4*>(sa + 8192 + aoff);
                uint32_t ah[4] = {ah4.x, ah4.y, ah4.z, ah4.w};
                uint32_t al[4] = {al4.x, al4.y, al4.z, al4.w};
                #pragma unroll
                for (int nt = 0; nt < 8; nt++) {
                    mma16(acc[mt][nt], ah, bh[nt]);
                    mma16(acc[mt][nt], ah, bl[nt]);
                    mma16(acc[mt][nt], al, bh[nt]);
                }
            }
        }
        __syncthreads();
    }

    // ---- epilogue ----
    const int h = blockIdx.x * 2 + warp_n;
    float wS0[8], wS1[8], wD0[8], wD1[8];
    #pragma unroll
    for (int nt = 0; nt < 8; nt++) {
        int r = nt * 8 + thr * 2;
        const float* ah = att + h * (2 * RR);
        wS0[nt] = ah[r];      wS1[nt] = ah[r + 1];
        wD0[nt] = ah[64 + r]; wD1[nt] = ah[64 + r + 1];
    }

    #pragma unroll
    for (int mt = 0; mt < 2; mt++) {
        float ssum[2] = {0.f, 0.f}, dsum[2] = {0.f, 0.f};
        #pragma unroll
        for (int nt = 0; nt < 8; nt++) {
            int row0 = bm + warp_m * 32 + mt * 16 + grp;
            int col  = bn + warp_n * 64 + nt * 8 + thr * 2;
            *reinterpret_cast<__half2*>(&g_hidden_h[(size_t)row0 * HR + col]) =
                __floats2half2_rn(acc[mt][nt][0], acc[mt][nt][1]);
            *reinterpret_cast<__half2*>(&g_hidden_h[(size_t)(row0 + 8) * HR + col]) =
                __floats2half2_rn(acc[mt][nt][2], acc[mt][nt][3]);
            ssum[0] = fmaf(acc[mt][nt][0], wS0[nt], fmaf(acc[mt][nt][1], wS1[nt], ssum[0]));
            dsum[0] = fmaf(acc[mt][nt][0], wD0[nt], fmaf(acc[mt][nt][1], wD1[nt], dsum[0]));
            ssum[1] = fmaf(acc[mt][nt][2], wS0[nt], fmaf(acc[mt][nt][3], wS1[nt], ssum[1]));
            dsum[1] = fmaf(acc[mt][nt][2], wD0[nt], fmaf(acc[mt][nt][3], wD1[nt], dsum[1]));
        }
        #pragma unroll
        for (int hf = 0; hf < 2; hf++) {
            ssum[hf] += __shfl_xor_sync(0xffffffffu, ssum[hf], 1);
            ssum[hf] += __shfl_xor_sync(0xffffffffu, ssum[hf], 2);
            dsum[hf] += __shfl_xor_sync(0xffffffffu, dsum[hf], 1);
            dsum[hf] += __shfl_xor_sync(0xffffffffu, dsum[hf], 2);
        }
        if (thr == 0) {
            #pragma unroll
            for (int hf = 0; hf < 2; hf++) {
                int row = bm + warp_m * 32 + mt * 16 + grp + hf * 8;
                g_asrc[h * NN + row] = ssum[hf];
                g_adstT[row * HH + h] = dsum[hf];
            }
        }
    }
}

// ---------------------------------------------------------------------------
// Kernel 3: fused sparse GAT attention + aggregation, one block per row i.
// Aggregation: 4-deep software pipeline -> 4 independent LDG.64 in flight.
// ---------------------------------------------------------------------------
#define SCHUNK 256
__global__ __launch_bounds__(512) void gat_row_kernel(
    const float* __restrict__ adj,
    const float* __restrict__ bias,
    float* __restrict__ out)
{
    __shared__ int   s_nbr[NN];            // 16 KB
    __shared__ __align__(16) float s_p[HH * SCHUNK];   // 8 KB (also reduce scratch)
    __shared__ float s_l[HH], s_asrc[HH];
    __shared__ unsigned s_wsum[16], s_woff[16];
    __shared__ int s_L;

    const int i   = blockIdx.x;
    const int tid = threadIdx.x;
    const int wid = tid >> 5;
    const int lane = tid & 31;

    // Phase A: ordered neighbor compaction (deterministic, no atomics)
    const float* adjRow = adj + (size_t)i * NN;
    const int base = tid * 8;
    float4 v0 = *reinterpret_cast<const float4*>(adjRow + base);
    float4 v1 = *reinterpret_cast<const float4*>(adjRow + base + 4);
    unsigned mask = 0;
    mask |= (v0.x != 0.f) ? 1u   : 0u;
    mask |= (v0.y != 0.f) ? 2u   : 0u;
    mask |= (v0.z != 0.f) ? 4u   : 0u;
    mask |= (v0.w != 0.f) ? 8u   : 0u;
    mask |= (v1.x != 0.f) ? 16u  : 0u;
    mask |= (v1.y != 0.f) ? 32u  : 0u;
    mask |= (v1.z != 0.f) ? 64u  : 0u;
    mask |= (v1.w != 0.f) ? 128u : 0u;
    unsigned cnt_t = __popc(mask);

    unsigned inc = cnt_t;
    #pragma unroll
    for (int d = 1; d < 32; d <<= 1) {
        unsigned o = __shfl_up_sync(0xffffffffu, inc, d);
        if (lane >= d) inc += o;
    }
    if (lane == 31) s_wsum[wid] = inc;

    if (tid < 8) { s_l[tid] = 0.f; s_asrc[tid] = g_asrc[tid * NN + i]; }
    __syncthreads();

    if (tid < 32) {
        unsigned v = (tid < 16) ? s_wsum[tid] : 0u;
        unsigned in2 = v;
        #pragma unroll
        for (int d = 1; d < 16; d <<= 1) {
            unsigned o = __shfl_up_sync(0xffffffffu, in2, d);
            if (lane >= d) in2 += o;
        }
        if (tid < 16) s_woff[tid] = in2 - v;
        if (tid == 15) s_L = (int)in2;
    }
    __syncthreads();

    {
        int off = (int)(s_woff[wid] + (inc - cnt_t));
        unsigned m = mask;
        while (m) {
            int q = __ffs(m) - 1;
            s_nbr[off++] = base + q;
            m &= m - 1;
        }
    }
    __syncthreads();

    const int L = s_L;
    const size_t ibase = (size_t)i * NN;
    const int sub  = tid >> 7;         // 0..3 neighbor subset
    const int hr4  = tid & 127;        // 4-col group of hidden
    const int hAgg = hr4 >> 4;         // head for aggregation
    float4 a4 = make_float4(0.f, 0.f, 0.f, 0.f);

    for (int c0 = 0; c0 < L; c0 += SCHUNK) {
        const int cnt = min(SCHUNK, L - c0);
        // score phase: kk = tid&255, head group hg = tid>>8 (4 heads each)
        {
            const int kk = tid & 255;
            const int hg = tid >> 8;
            if (kk < cnt) {
                int j = s_nbr[c0 + kk];
                float4 ad = *reinterpret_cast<const float4*>(g_adstT + j * HH + hg * 4);
                float b = EPSB * __ldg(bias + ibase + j);
                const float* adp = &ad.x;
                #pragma unroll
                for (int q = 0; q < 4; q++) {
                    int hh = hg * 4 + q;
                    float pre = s_asrc[hh] + adp[q] + b;
                    pre = (pre >= 0.f) ? pre : ALPHA * pre;
                    s_p[hh * SCHUNK + kk] = __expf(pre);
                }
            } else {
                #pragma unroll
                for (int q = 0; q < 4; q++)
                    s_p[(hg * 4 + q) * SCHUNK + kk] = 0.f;
            }
        }
        __syncthreads();

        // per-head sum (warps 0-7) — runs alongside aggregation
        if (wid < HH) {
            float sloc = 0.f;
            #pragma unroll
            for (int q = 0; q < 8; q++)
                sloc += s_p[wid * SCHUNK + lane + q * 32];
            #pragma unroll
            for (int d = 16; d; d >>= 1)
                sloc += __shfl_xor_sync(0xffffffffu, sloc, d);
            if (lane == 0) s_l[wid] += sloc;
        }

        // aggregation: 4-deep pipeline, 4 independent LDG.64 per iteration
        const float* ph = &s_p[hAgg * SCHUNK];
        const __half* hb = g_hidden_h + hr4 * 4;
        for (int kk0 = sub; kk0 < cnt; kk0 += 16) {
            int jj[4]; float pp[4];
            #pragma unroll
            for (int q = 0; q < 4; q++) {
                int kk = kk0 + q * 4;
                int kkc = min(kk, cnt - 1);
                jj[q] = s_nbr[c0 + kkc];
                pp[q] = (kk < cnt) ? ph[kkc] : 0.f;
            }
            uint2 uu[4];
            #pragma unroll
            for (int q = 0; q < 4; q++)
                uu[q] = *reinterpret_cast<const uint2*>(hb + (size_t)jj[q] * HR);
            #pragma unroll
            for (int q = 0; q < 4; q++) {
                float2 f0 = __half22float2(*reinterpret_cast<__half2*>(&uu[q].x));
                float2 f1 = __half22float2(*reinterpret_cast<__half2*>(&uu[q].y));
                a4.x = fmaf(pp[q], f0.x, a4.x);
                a4.y = fmaf(pp[q], f0.y, a4.y);
                a4.z = fmaf(pp[q], f1.x, a4.z);
                a4.w = fmaf(pp[q], f1.y, a4.w);
            }
        }
        __syncthreads();
    }

    // cross-subset reduction via s_p scratch (4 x 128 float4 = 8 KB)
    float4* red = reinterpret_cast<float4*>(s_p);
    red[sub * 128 + hr4] = a4;
    __syncthreads();
    if (tid < 128) {
        float4 r0 = red[tid], r1 = red[128 + tid],
               r2 = red[256 + tid], r3 = red[384 + tid];
        float invl = 1.f / s_l[tid >> 4];
        float4 o;
        o.x = (r0.x + r1.x + r2.x + r3.x) * invl;
        o.y = (r0.y + r1.y + r2.y + r3.y) * invl;
        o.z = (r0.z + r1.z + r2.z + r3.z) * invl;
        o.w = (r0.w + r1.w + r2.w + r3.w) * invl;
        *reinterpret_cast<float4*>(out + (size_t)i * HR + tid * 4) = o;
    }
}

// ---------------------------------------------------------------------------
extern "C" void kernel_launch(void* const* d_in, const int* in_sizes, int n_in,
                              void* d_out, int out_size)
{
    const float* node = (const float*)d_in[0];   // [4096,512]
    const float* adj  = (const float*)d_in[1];   // [4096,4096]
    const float* W    = (const float*)d_in[2];   // [8,512,64]
    const float* att  = (const float*)d_in[3];   // [8,128]
    const float* bias = (const float*)d_in[4];   // [4096,4096]
    float* out = (float*)d_out;                  // [4096,512]

    cudaFuncSetAttribute(gemm_mma_kernel,
                         cudaFuncAttributeMaxDynamicSharedMemorySize, 2 * STAGE);

    preA_kernel<<<NN * FF / 8 / 256, 256>>>(node);
    preB_kernel<<<HR * FF / 4 / 256, 256>>>(W);
    gemm_mma_kernel<<<dim3(HR / 128, NN / 128), 256, 2 * STAGE>>>(att);
    gat_row_kernel<<<NN, 512>>>(adj, bias, out);
}